// round 14
// baseline (speedup 1.0000x reference)
#include <cuda_runtime.h>
#include <cuda_bf16.h>
#include <cuda_fp16.h>
#include <cstdint>

#define NUM_NODES 100000
#define HIDDEN    128
#define OFFS      2
#define MAX_E     1700000
#define MAX_SEQ   32768

// ---------------- device scratch ----------------
__device__ int   g_deg[NUM_NODES];
__device__ int   g_fill[NUM_NODES];       // after prep: CSR write cursor (= rowptr)
__device__ int   g_rowptr[NUM_NODES + 1];
__device__ int   g_blksum[2048];
__device__ int   g_colidx[MAX_E];
__device__ float g_dinv[NUM_NODES];
__device__ int   g_need[NUM_NODES];
__device__ int   g_slot[NUM_NODES];
__device__ int   g_list[MAX_SEQ];
__device__ int   g_cnt;
__device__ unsigned g_bar;
__device__ unsigned g_gen;
__device__ __half g_y16[(size_t)NUM_NODES * HIDDEN];
__device__ __half g_h16[(size_t)NUM_NODES * HIDDEN];
__device__ __half g_a2[(size_t)MAX_SEQ * HIDDEN];
__device__ float  g_z[(size_t)MAX_SEQ * HIDDEN];
__device__ __nv_bfloat16 g_w0h[HIDDEN * HIDDEN];
__device__ __nv_bfloat16 g_w0l[HIDDEN * HIDDEN];
__device__ __nv_bfloat16 g_w1h[HIDDEN * HIDDEN];
__device__ __nv_bfloat16 g_w1l[HIDDEN * HIDDEN];

// ---------------- helpers ----------------
__device__ __forceinline__ uint32_t smem_u32(const void* p) {
    uint32_t a;
    asm("{ .reg .u64 t; cvta.to.shared.u64 t, %1; cvt.u32.u64 %0, t; }" : "=r"(a) : "l"(p));
    return a;
}
__device__ __forceinline__ void ldsm_x4(uint32_t addr, uint32_t& r0, uint32_t& r1,
                                        uint32_t& r2, uint32_t& r3) {
    asm volatile("ldmatrix.sync.aligned.m8n8.x4.shared.b16 {%0,%1,%2,%3}, [%4];"
                 : "=r"(r0), "=r"(r1), "=r"(r2), "=r"(r3) : "r"(addr));
}
__device__ __forceinline__ void mma_bf16(float* c, const uint32_t* a, uint32_t b0, uint32_t b1) {
    asm volatile(
        "mma.sync.aligned.m16n8k16.row.col.f32.bf16.bf16.f32 "
        "{%0,%1,%2,%3}, {%4,%5,%6,%7}, {%8,%9}, {%0,%1,%2,%3};"
        : "+f"(c[0]), "+f"(c[1]), "+f"(c[2]), "+f"(c[3])
        : "r"(a[0]), "r"(a[1]), "r"(a[2]), "r"(a[3]), "r"(b0), "r"(b1));
}
__device__ __forceinline__ void grid_barrier(int nblk) {
    __syncthreads();
    if (threadIdx.x == 0) {
        __threadfence();
        unsigned gen = *(volatile unsigned*)&g_gen;
        if (atomicAdd(&g_bar, 1u) == (unsigned)nblk - 1u) {
            atomicExch(&g_bar, 0u);
            __threadfence();
            atomicAdd(&g_gen, 1u);
        } else {
            while (*(volatile unsigned*)&g_gen == gen) { __nanosleep(64); }
            __threadfence();
        }
    }
    __syncthreads();
}

// ---------------- persistent prep: everything except CSR fill ----------------
__global__ __launch_bounds__(256, 8)
void k_prep(const float* __restrict__ W0, const float* __restrict__ W1,
            const int* __restrict__ dst, const int* __restrict__ seq,
            int E, int S, int nblk, int chunk) {
    const int tid = threadIdx.x, bid = blockIdx.x;
    const int gtid = bid * 256 + tid;
    const int gstride = nblk * 256;
    __shared__ int sbuf[256];

    for (int i = gtid; i < NUM_NODES; i += gstride) {
        g_deg[i] = 0; g_need[i] = 0;
    }
    if (gtid == 0) g_cnt = 0;
    for (int i = gtid; i < 2 * HIDDEN * HIDDEN; i += gstride) {
        int which = i >> 14, idx = i & 16383;   // idx = k*128+n
        float w = (which ? W1 : W0)[idx];
        int k = idx >> 7, n = idx & 127;
        __nv_bfloat16 h = __float2bfloat16(w);
        (which ? g_w1h : g_w0h)[n * 128 + k] = h;
        (which ? g_w1l : g_w0l)[n * 128 + k] = __float2bfloat16(w - __bfloat162float(h));
    }
    grid_barrier(nblk);

    for (int e = gtid; e < E; e += gstride) atomicAdd(&g_deg[dst[e]], 1);
    for (int p = gtid; p < S; p += gstride) {
        int v = seq[p];
        if (v >= 0) g_need[v] = 1;
    }
    grid_barrier(nblk);

    {
        int start = bid * chunk;
        int len = NUM_NODES - start;
        if (len > chunk) len = chunk;
        int acc = 0;
        for (int i = tid; i < len; i += 256) acc += g_deg[start + i];
        sbuf[tid] = acc;
        __syncthreads();
        #pragma unroll
        for (int off = 128; off > 0; off >>= 1) {
            if (tid < off) sbuf[tid] += sbuf[tid + off];
            __syncthreads();
        }
        if (tid == 0) g_blksum[bid] = sbuf[0];
    }
    grid_barrier(nblk);

    if (bid == 0) {
        int ele = (nblk + 255) >> 8;
        int base_i = tid * ele;
        int vals[8];
        int tsum = 0;
        for (int q = 0; q < ele && q < 8; q++) {
            int ii = base_i + q;
            vals[q] = (ii < nblk) ? g_blksum[ii] : 0;
            tsum += vals[q];
        }
        sbuf[tid] = tsum;
        __syncthreads();
        #pragma unroll
        for (int off = 1; off < 256; off <<= 1) {
            int t = (tid >= off) ? sbuf[tid - off] : 0;
            __syncthreads();
            sbuf[tid] += t;
            __syncthreads();
        }
        int run = sbuf[tid] - tsum;
        for (int q = 0; q < ele && q < 8; q++) {
            int ii = base_i + q;
            if (ii < nblk) g_blksum[ii] = run;
            run += vals[q];
        }
    }
    grid_barrier(nblk);

    {
        int start = bid * chunk;
        int len = NUM_NODES - start;
        if (len > chunk) len = chunk;
        if (len < 0) len = 0;
        int run = (start < NUM_NODES) ? g_blksum[bid] : 0;
        for (int base = 0; base < chunk; base += 256) {
            int li = base + tid;
            int idx = start + li;
            int val = (li < len) ? g_deg[idx] : 0;
            sbuf[tid] = val;
            __syncthreads();
            #pragma unroll
            for (int off = 1; off < 256; off <<= 1) {
                int t = (tid >= off) ? sbuf[tid - off] : 0;
                __syncthreads();
                sbuf[tid] += t;
                __syncthreads();
            }
            int excl = sbuf[tid] - val;
            if (li < len) {
                int rp = run + excl;
                g_rowptr[idx] = rp;
                g_fill[idx]   = rp;
                g_dinv[idx] = rsqrtf((float)(val + 1));
                if (g_need[idx]) {
                    int s = atomicAdd(&g_cnt, 1);
                    g_slot[idx] = s;
                    g_list[s] = idx;
                }
            }
            int tot = sbuf[255];
            __syncthreads();
            run += tot;
        }
        if (gtid == 0) g_rowptr[NUM_NODES] = E;
    }
}

// ---------------- CSR fill (concurrent with gemm1) ----------------
__global__ __launch_bounds__(256)
void k_fill(const int* __restrict__ src, const int* __restrict__ dst, int E) {
    int e = blockIdx.x * 256 + threadIdx.x;
    if (e < E) {
        int p = atomicAdd(&g_fill[dst[e]], 1);
        g_colidx[p] = src[e];
    }
}

// ---------------- bf16x3 tensor GEMM (split A in-smem) ----------------
#define LDS_STRIDE 136
#define TILE_HALFS (128 * LDS_STRIDE)
#define GEMM_SMEM  (4 * TILE_HALFS * 2)

template <bool FP16IN, bool SCALED, bool COMPACT, bool FOUT>
__global__ __launch_bounds__(256)
void k_gemm(const void* __restrict__ Av,
            const __nv_bfloat16* __restrict__ Bh, const __nv_bfloat16* __restrict__ Bl,
            const float* __restrict__ bias, void* __restrict__ Cv, int Mfix) {
    const int M = COMPACT ? g_cnt : Mfix;
    const int brow = blockIdx.x * 128;
    if (brow >= M) return;

    extern __shared__ __align__(16) __nv_bfloat16 sm[];
    __nv_bfloat16* sAh = sm;
    __nv_bfloat16* sAl = sm + TILE_HALFS;
    __nv_bfloat16* sBh = sm + 2 * TILE_HALFS;
    __nv_bfloat16* sBl = sm + 3 * TILE_HALFS;

    const int tid = threadIdx.x, wid = tid >> 5, lane = tid & 31;

    for (int i = tid; i < 2048; i += 256) {
        int r  = i >> 4;
        int c8 = (i & 15) << 3;
        int d  = r * LDS_STRIDE + c8;
        int grow = brow + r;
        float f[8];
        if (grow < M) {
            if (FP16IN) {
                const __half* A = (const __half*)Av;
                uint4 v = *reinterpret_cast<const uint4*>(A + (size_t)grow * 128 + c8);
                const __half2* hp = reinterpret_cast<const __half2*>(&v);
                #pragma unroll
                for (int q = 0; q < 4; q++) {
                    float2 fq = __half22float2(hp[q]);
                    f[q * 2] = fq.x; f[q * 2 + 1] = fq.y;
                }
            } else {
                const float* A = (const float*)Av;
                float4 a0 = *reinterpret_cast<const float4*>(A + (size_t)grow * 128 + c8);
                float4 a1 = *reinterpret_cast<const float4*>(A + (size_t)grow * 128 + c8 + 4);
                f[0] = a0.x; f[1] = a0.y; f[2] = a0.z; f[3] = a0.w;
                f[4] = a1.x; f[5] = a1.y; f[6] = a1.z; f[7] = a1.w;
            }
        } else {
            #pragma unroll
            for (int q = 0; q < 8; q++) f[q] = 0.f;
        }
        __align__(16) unsigned short hh[8];
        __align__(16) unsigned short ll[8];
        #pragma unroll
        for (int q = 0; q < 8; q++) {
            __nv_bfloat16 hi = __float2bfloat16(f[q]);
            __nv_bfloat16 lo = __float2bfloat16(f[q] - __bfloat162float(hi));
            hh[q] = __bfloat16_as_ushort(hi);
            ll[q] = __bfloat16_as_ushort(lo);
        }
        *reinterpret_cast<ushort4*>(sAh + d)     = *reinterpret_cast<ushort4*>(hh);
        *reinterpret_cast<ushort4*>(sAh + d + 4) = *reinterpret_cast<ushort4*>(hh + 4);
        *reinterpret_cast<ushort4*>(sAl + d)     = *reinterpret_cast<ushort4*>(ll);
        *reinterpret_cast<ushort4*>(sAl + d + 4) = *reinterpret_cast<ushort4*>(ll + 4);
        *reinterpret_cast<uint4*>(sBh + d) =
            *reinterpret_cast<const uint4*>(Bh + (size_t)r * 128 + c8);
        *reinterpret_cast<uint4*>(sBl + d) =
            *reinterpret_cast<const uint4*>(Bl + (size_t)r * 128 + c8);
    }
    __syncthreads();

    const int mb = (wid & 3) * 32;
    const int nb = (wid >> 2) * 64;

    float acc[2][8][4];
    #pragma unroll
    for (int i = 0; i < 2; i++)
        #pragma unroll
        for (int j = 0; j < 8; j++)
            #pragma unroll
            for (int q = 0; q < 4; q++) acc[i][j][q] = 0.0f;

    const int lrow  = lane & 15;
    const int lbyte = (lane >> 4) << 4;

    #pragma unroll
    for (int pass = 0; pass < 3; pass++) {
        const __nv_bfloat16* pA = (pass == 1) ? sAl : sAh;
        const __nv_bfloat16* pB = (pass == 2) ? sBl : sBh;
        #pragma unroll
        for (int k16 = 0; k16 < 8; k16++) {
            int kb = k16 * 16;
            uint32_t a[2][4];
            #pragma unroll
            for (int i = 0; i < 2; i++) {
                uint32_t ad = smem_u32(pA + (mb + i * 16 + lrow) * LDS_STRIDE + kb) + lbyte;
                ldsm_x4(ad, a[i][0], a[i][1], a[i][2], a[i][3]);
            }
            uint32_t b[4][4];
            #pragma unroll
            for (int j = 0; j < 4; j++) {
                uint32_t ad = smem_u32(pB + (nb + j * 16 + lrow) * LDS_STRIDE + kb) + lbyte;
                ldsm_x4(ad, b[j][0], b[j][1], b[j][2], b[j][3]);
            }
            #pragma unroll
            for (int i = 0; i < 2; i++)
                #pragma unroll
                for (int j = 0; j < 4; j++) {
                    mma_bf16(acc[i][j * 2 + 0], a[i], b[j][0], b[j][2]);
                    mma_bf16(acc[i][j * 2 + 1], a[i], b[j][1], b[j][3]);
                }
        }
    }

    const int tr = lane >> 2, tc = (lane & 3) * 2;
    #pragma unroll
    for (int i = 0; i < 2; i++) {
        int row0 = brow + mb + i * 16 + tr;
        float s0 = 1.f, s1 = 1.f;
        if (SCALED) {
            if (row0 < M)     s0 = g_dinv[row0];
            if (row0 + 8 < M) s1 = g_dinv[row0 + 8];
        }
        #pragma unroll
        for (int j = 0; j < 8; j++) {
            int col = nb + j * 8 + tc;
            if (FOUT) {
                float* C = (float*)Cv;
                float bx = bias[col], by = bias[col + 1];
                if (row0 < M) {
                    float2 o = make_float2(acc[i][j][0] + bx, acc[i][j][1] + by);
                    *reinterpret_cast<float2*>(C + (size_t)row0 * 128 + col) = o;
                }
                if (row0 + 8 < M) {
                    float2 o = make_float2(acc[i][j][2] + bx, acc[i][j][3] + by);
                    *reinterpret_cast<float2*>(C + (size_t)(row0 + 8) * 128 + col) = o;
                }
            } else {
                __half* C = (__half*)Cv;
                if (row0 < M)
                    *reinterpret_cast<__half2*>(C + (size_t)row0 * 128 + col) =
                        __floats2half2_rn(acc[i][j][0] * s0, acc[i][j][1] * s0);
                if (row0 + 8 < M)
                    *reinterpret_cast<__half2*>(C + (size_t)(row0 + 8) * 128 + col) =
                        __floats2half2_rn(acc[i][j][2] * s1, acc[i][j][3] * s1);
            }
        }
    }
}

// ---------------- aggregation: 2 rows/LDG.128 + fp16 batch accumulation ----------------
// fl = lane&15 -> 16B feature chunk; half = lane>>4 -> which edge of a pair.
// Per 32-edge batch: two independent fp16 accumulator chains, one fp32 convert.
__device__ __forceinline__ void agg_core8(const __half* __restrict__ x, int node, int lane,
                                          float* acc) {
    const uint4* xr = reinterpret_cast<const uint4*>(x);   // 16 uint4 per 128-feat row
    const int fl = lane & 15, half = lane >> 4;

    #pragma unroll
    for (int q = 0; q < 8; q++) acc[q] = 0.f;
    // self term: half 0 only (avoid double count after butterfly)
    {
        uint4 su = xr[(size_t)node * 16 + fl];
        if (half == 0) {
            __half2* sh = reinterpret_cast<__half2*>(&su);
            #pragma unroll
            for (int q = 0; q < 4; q++) {
                float2 f = __half22float2(sh[q]);
                acc[q * 2]     += f.x;
                acc[q * 2 + 1] += f.y;
            }
        }
    }

    const __half2 zero2 = __float2half2_rn(0.f);
    int b = g_rowptr[node], e = g_rowptr[node + 1];
    for (int base = b; base < e; base += 32) {
        int m = min(32, e - base);
        int c = (lane < m) ? g_colidx[base + lane] : 0;
        __half2 ah0 = zero2, ah1 = zero2, ah2 = zero2, ah3 = zero2;   // chain A
        __half2 bh0 = zero2, bh1 = zero2, bh2 = zero2, bh3 = zero2;   // chain B
        int j = 0;
        // 4 edges/iter: 2 LDG.128, 2 SHFL, 8 HADD2 (two independent chains)
        for (; j + 4 <= m; j += 4) {
            int sA = __shfl_sync(0xFFFFFFFFu, c, j + half);
            int sB = __shfl_sync(0xFFFFFFFFu, c, j + 2 + half);
            uint4 uA = xr[(size_t)sA * 16 + fl];
            uint4 uB = xr[(size_t)sB * 16 + fl];
            __half2* ha = reinterpret_cast<__half2*>(&uA);
            __half2* hb = reinterpret_cast<__half2*>(&uB);
            ah0 = __hadd2(ah0, ha[0]); ah1 = __hadd2(ah1, ha[1]);
            ah2 = __hadd2(ah2, ha[2]); ah3 = __hadd2(ah3, ha[3]);
            bh0 = __hadd2(bh0, hb[0]); bh1 = __hadd2(bh1, hb[1]);
            bh2 = __hadd2(bh2, hb[2]); bh3 = __hadd2(bh3, hb[3]);
        }
        // 2 edges
        for (; j + 2 <= m; j += 2) {
            int s = __shfl_sync(0xFFFFFFFFu, c, j + half);
            uint4 u = xr[(size_t)s * 16 + fl];
            __half2* h = reinterpret_cast<__half2*>(&u);
            ah0 = __hadd2(ah0, h[0]); ah1 = __hadd2(ah1, h[1]);
            ah2 = __hadd2(ah2, h[2]); ah3 = __hadd2(ah3, h[3]);
        }
        // odd tail: half 0 only
        if (j < m) {
            int s = __shfl_sync(0xFFFFFFFFu, c, j);
            uint4 u = xr[(size_t)s * 16 + fl];
            if (half == 0) {
                __half2* h = reinterpret_cast<__half2*>(&u);
                ah0 = __hadd2(ah0, h[0]); ah1 = __hadd2(ah1, h[1]);
                ah2 = __hadd2(ah2, h[2]); ah3 = __hadd2(ah3, h[3]);
            }
        }
        // merge chains and convert once per batch
        ah0 = __hadd2(ah0, bh0); ah1 = __hadd2(ah1, bh1);
        ah2 = __hadd2(ah2, bh2); ah3 = __hadd2(ah3, bh3);
        float2 f0 = __half22float2(ah0), f1 = __half22float2(ah1);
        float2 f2 = __half22float2(ah2), f3 = __half22float2(ah3);
        acc[0] += f0.x; acc[1] += f0.y;
        acc[2] += f1.x; acc[3] += f1.y;
        acc[4] += f2.x; acc[5] += f2.y;
        acc[6] += f3.x; acc[7] += f3.y;
    }
    // butterfly: merge the two half-warp partials
    #pragma unroll
    for (int q = 0; q < 8; q++)
        acc[q] += __shfl_xor_sync(0xFFFFFFFFu, acc[q], 16);
}

// layer-1 agg: h'[v] = dinv[v] * relu(dinv[v]*acc + b0)
__global__ __launch_bounds__(256)
void k_agg(const __half* __restrict__ x, const float* __restrict__ bias,
           __half* __restrict__ out, int n) {
    int gw   = (blockIdx.x * blockDim.x + threadIdx.x) >> 5;
    int lane = threadIdx.x & 31;
    if (gw >= n) return;
    float acc[8];
    agg_core8(x, gw, lane, acc);
    float dv = g_dinv[gw];
    const int fl = lane & 15, half = lane >> 4;
    const int col = fl * 8 + half * 4;
    float4 bv = *reinterpret_cast<const float4*>(bias + col);
    float o0 = fmaxf(fmaf(acc[half * 4 + 0], dv, bv.x), 0.f) * dv;
    float o1 = fmaxf(fmaf(acc[half * 4 + 1], dv, bv.y), 0.f) * dv;
    float o2 = fmaxf(fmaf(acc[half * 4 + 2], dv, bv.z), 0.f) * dv;
    float o3 = fmaxf(fmaf(acc[half * 4 + 3], dv, bv.w), 0.f) * dv;
    uint2 u;
    __half2 h0 = __floats2half2_rn(o0, o1);
    __half2 h1 = __floats2half2_rn(o2, o3);
    u.x = *reinterpret_cast<uint32_t*>(&h0);
    u.y = *reinterpret_cast<uint32_t*>(&h1);
    *reinterpret_cast<uint2*>(out + (size_t)gw * 128 + col) = u;
}

// layer-2 agg (compact): a2[slot] = dinv[v] * acc  (fp16)
__global__ __launch_bounds__(256)
void k_agg_sel(const __half* __restrict__ x, __half* __restrict__ out) {
    int gw   = (blockIdx.x * blockDim.x + threadIdx.x) >> 5;
    int lane = threadIdx.x & 31;
    if (gw >= g_cnt) return;
    int node = g_list[gw];
    float acc[8];
    agg_core8(x, node, lane, acc);
    float dv = g_dinv[node];
    const int fl = lane & 15, half = lane >> 4;
    const int col = fl * 8 + half * 4;
    uint2 u;
    __half2 h0 = __floats2half2_rn(acc[half * 4 + 0] * dv, acc[half * 4 + 1] * dv);
    __half2 h1 = __floats2half2_rn(acc[half * 4 + 2] * dv, acc[half * 4 + 3] * dv);
    u.x = *reinterpret_cast<uint32_t*>(&h0);
    u.y = *reinterpret_cast<uint32_t*>(&h1);
    *reinterpret_cast<uint2*>(out + (size_t)gw * 128 + col) = u;
}

// ---------------- final gather ----------------
__global__ __launch_bounds__(256)
void k_gather(const float* __restrict__ z, const float* __restrict__ emb,
              const int* __restrict__ seq, float* __restrict__ out, int S) {
    int t = blockIdx.x * blockDim.x + threadIdx.x;
    int pos = t >> 5, lane = t & 31;
    if (pos >= S) return;
    int v = seq[pos];
    const float4* srcp;
    size_t row;
    if (v >= 0) { srcp = reinterpret_cast<const float4*>(z);   row = (size_t)g_slot[v]; }
    else        { srcp = reinterpret_cast<const float4*>(emb); row = (size_t)(v + OFFS + NUM_NODES); }
    reinterpret_cast<float4*>(out)[(size_t)pos * 32 + lane] = srcp[row * 32 + lane];
}

// ---------------- host launch ----------------
extern "C" void kernel_launch(void* const* d_in, const int* in_sizes, int n_in,
                              void* d_out, int out_size) {
    const float* emb = (const float*)d_in[0];
    const float* W0  = (const float*)d_in[1];
    const float* b0  = (const float*)d_in[2];
    const float* W1  = (const float*)d_in[3];
    const float* b1  = (const float*)d_in[4];
    const int*   ei  = (const int*)d_in[5];
    const int*   seq = (const int*)d_in[6];

    int E = in_sizes[5] / 2;
    int S = in_sizes[6];
    const int* src = ei;
    const int* dst = ei + E;

    float *z = nullptr;
    __half *y16 = nullptr, *h16 = nullptr, *a2 = nullptr;
    __nv_bfloat16 *w0h = nullptr, *w0l = nullptr, *w1h = nullptr, *w1l = nullptr;
    cudaGetSymbolAddress((void**)&z,   g_z);
    cudaGetSymbolAddress((void**)&y16, g_y16);
    cudaGetSymbolAddress((void**)&h16, g_h16);
    cudaGetSymbolAddress((void**)&a2,  g_a2);
    cudaGetSymbolAddress((void**)&w0h, g_w0h);
    cudaGetSymbolAddress((void**)&w0l, g_w0l);
    cudaGetSymbolAddress((void**)&w1h, g_w1h);
    cudaGetSymbolAddress((void**)&w1l, g_w1l);

    cudaFuncSetAttribute((const void*)k_gemm<false, true, false, false>,
                         cudaFuncAttributeMaxDynamicSharedMemorySize, GEMM_SMEM);
    cudaFuncSetAttribute((const void*)k_gemm<true, false, true, true>,
                         cudaFuncAttributeMaxDynamicSharedMemorySize, GEMM_SMEM);

    int dev = 0, nsm = 0;
    cudaGetDevice(&dev);
    cudaDeviceGetAttribute(&nsm, cudaDevAttrMultiProcessorCount, dev);
    // fewer blocks -> cheaper grid barriers; still atomic/L2-throughput bound
    int nblk = nsm * 4;
    if (nblk > 2048) nblk = 2048;
    int chunk = (NUM_NODES + nblk - 1) / nblk;

    static bool s_init = false;
    static cudaStream_t s_fill;
    static cudaEvent_t s_evA, s_evB;
    if (!s_init) {
        cudaStreamCreateWithFlags(&s_fill, cudaStreamNonBlocking);
        cudaEventCreateWithFlags(&s_evA, cudaEventDisableTiming);
        cudaEventCreateWithFlags(&s_evB, cudaEventDisableTiming);
        s_init = true;
    }

    // 0) prep
    k_prep<<<nblk, 256>>>(W0, W1, dst, seq, E, S, nblk, chunk);
    // fork: fill concurrent with gemm1
    cudaEventRecord(s_evA, 0);
    cudaStreamWaitEvent(s_fill, s_evA, 0);
    k_fill<<<(E + 255) / 256, 256, 0, s_fill>>>(src, dst, E);
    cudaEventRecord(s_evB, s_fill);
    // 1) Y0' = dinv * (emb @ W0)
    k_gemm<false, true, false, false><<<(NUM_NODES + 127) / 128, 256, GEMM_SMEM>>>(
        emb, w0h, w0l, nullptr, y16, NUM_NODES);
    cudaStreamWaitEvent(0, s_evB, 0);
    // 2) h' = dinv * relu(agg(Y0') + b0)
    k_agg<<<(NUM_NODES * 32 + 255) / 256, 256>>>(y16, b0, h16, NUM_NODES);
    // 3) a2 = agg_sel(h')
    k_agg_sel<<<(MAX_SEQ * 32 + 255) / 256, 256>>>(h16, a2);
    // 4) z = a2 @ W1 + b1
    k_gemm<true, false, true, true><<<(MAX_SEQ + 127) / 128, 256, GEMM_SMEM>>>(
        a2, w1h, w1l, b1, z, 0);
    // 5) gather
    k_gather<<<(S * 32 + 255) / 256, 256>>>(z, emb, seq, (float*)d_out, S);
}

// round 15
// speedup vs baseline: 1.0081x; 1.0081x over previous
#include <cuda_runtime.h>
#include <cuda_bf16.h>
#include <cuda_fp16.h>
#include <cstdint>

#define NUM_NODES 100000
#define HIDDEN    128
#define OFFS      2
#define MAX_E     1700000
#define MAX_SEQ   32768

// ---------------- device scratch ----------------
__device__ int   g_deg[NUM_NODES];
__device__ int   g_fill[NUM_NODES];       // after prep: CSR write cursor (= rowptr)
__device__ int   g_rowptr[NUM_NODES + 1];
__device__ int   g_blksum[2048];
__device__ int   g_colidx[MAX_E];
__device__ float g_dinv[NUM_NODES];
__device__ int   g_need[NUM_NODES];
__device__ int   g_slot[NUM_NODES];
__device__ int   g_list[MAX_SEQ];
__device__ int   g_cnt;
__device__ unsigned g_bar;
__device__ unsigned g_gen;
__device__ __half g_y16[(size_t)NUM_NODES * HIDDEN];
__device__ __half g_h16[(size_t)NUM_NODES * HIDDEN];
__device__ __half g_a2[(size_t)MAX_SEQ * HIDDEN];
__device__ float  g_z[(size_t)MAX_SEQ * HIDDEN];
__device__ __nv_bfloat16 g_w0h[HIDDEN * HIDDEN];
__device__ __nv_bfloat16 g_w0l[HIDDEN * HIDDEN];
__device__ __nv_bfloat16 g_w1h[HIDDEN * HIDDEN];
__device__ __nv_bfloat16 g_w1l[HIDDEN * HIDDEN];

// ---------------- helpers ----------------
__device__ __forceinline__ uint32_t smem_u32(const void* p) {
    uint32_t a;
    asm("{ .reg .u64 t; cvta.to.shared.u64 t, %1; cvt.u32.u64 %0, t; }" : "=r"(a) : "l"(p));
    return a;
}
__device__ __forceinline__ void ldsm_x4(uint32_t addr, uint32_t& r0, uint32_t& r1,
                                        uint32_t& r2, uint32_t& r3) {
    asm volatile("ldmatrix.sync.aligned.m8n8.x4.shared.b16 {%0,%1,%2,%3}, [%4];"
                 : "=r"(r0), "=r"(r1), "=r"(r2), "=r"(r3) : "r"(addr));
}
__device__ __forceinline__ void mma_bf16(float* c, const uint32_t* a, uint32_t b0, uint32_t b1) {
    asm volatile(
        "mma.sync.aligned.m16n8k16.row.col.f32.bf16.bf16.f32 "
        "{%0,%1,%2,%3}, {%4,%5,%6,%7}, {%8,%9}, {%0,%1,%2,%3};"
        : "+f"(c[0]), "+f"(c[1]), "+f"(c[2]), "+f"(c[3])
        : "r"(a[0]), "r"(a[1]), "r"(a[2]), "r"(a[3]), "r"(b0), "r"(b1));
}
__device__ __forceinline__ void grid_barrier(int nblk) {
    __syncthreads();
    if (threadIdx.x == 0) {
        __threadfence();
        unsigned gen = *(volatile unsigned*)&g_gen;
        if (atomicAdd(&g_bar, 1u) == (unsigned)nblk - 1u) {
            atomicExch(&g_bar, 0u);
            __threadfence();
            atomicAdd(&g_gen, 1u);
        } else {
            while (*(volatile unsigned*)&g_gen == gen) { __nanosleep(64); }
            __threadfence();
        }
    }
    __syncthreads();
}

// ---------------- persistent prep: everything except CSR fill ----------------
__global__ __launch_bounds__(256, 8)
void k_prep(const float* __restrict__ W0, const float* __restrict__ W1,
            const int* __restrict__ dst, const int* __restrict__ seq,
            int E, int S, int nblk, int chunk) {
    const int tid = threadIdx.x, bid = blockIdx.x;
    const int gtid = bid * 256 + tid;
    const int gstride = nblk * 256;
    __shared__ int sbuf[256];

    for (int i = gtid; i < NUM_NODES; i += gstride) {
        g_deg[i] = 0; g_need[i] = 0;
    }
    if (gtid == 0) g_cnt = 0;
    for (int i = gtid; i < 2 * HIDDEN * HIDDEN; i += gstride) {
        int which = i >> 14, idx = i & 16383;   // idx = k*128+n
        float w = (which ? W1 : W0)[idx];
        int k = idx >> 7, n = idx & 127;
        __nv_bfloat16 h = __float2bfloat16(w);
        (which ? g_w1h : g_w0h)[n * 128 + k] = h;
        (which ? g_w1l : g_w0l)[n * 128 + k] = __float2bfloat16(w - __bfloat162float(h));
    }
    grid_barrier(nblk);

    for (int e = gtid; e < E; e += gstride) atomicAdd(&g_deg[dst[e]], 1);
    for (int p = gtid; p < S; p += gstride) {
        int v = seq[p];
        if (v >= 0) g_need[v] = 1;
    }
    grid_barrier(nblk);

    {
        int start = bid * chunk;
        int len = NUM_NODES - start;
        if (len > chunk) len = chunk;
        int acc = 0;
        for (int i = tid; i < len; i += 256) acc += g_deg[start + i];
        sbuf[tid] = acc;
        __syncthreads();
        #pragma unroll
        for (int off = 128; off > 0; off >>= 1) {
            if (tid < off) sbuf[tid] += sbuf[tid + off];
            __syncthreads();
        }
        if (tid == 0) g_blksum[bid] = sbuf[0];
    }
    grid_barrier(nblk);

    if (bid == 0) {
        int ele = (nblk + 255) >> 8;
        int base_i = tid * ele;
        int vals[8];
        int tsum = 0;
        for (int q = 0; q < ele && q < 8; q++) {
            int ii = base_i + q;
            vals[q] = (ii < nblk) ? g_blksum[ii] : 0;
            tsum += vals[q];
        }
        sbuf[tid] = tsum;
        __syncthreads();
        #pragma unroll
        for (int off = 1; off < 256; off <<= 1) {
            int t = (tid >= off) ? sbuf[tid - off] : 0;
            __syncthreads();
            sbuf[tid] += t;
            __syncthreads();
        }
        int run = sbuf[tid] - tsum;
        for (int q = 0; q < ele && q < 8; q++) {
            int ii = base_i + q;
            if (ii < nblk) g_blksum[ii] = run;
            run += vals[q];
        }
    }
    grid_barrier(nblk);

    {
        int start = bid * chunk;
        int len = NUM_NODES - start;
        if (len > chunk) len = chunk;
        if (len < 0) len = 0;
        int run = (start < NUM_NODES) ? g_blksum[bid] : 0;
        for (int base = 0; base < chunk; base += 256) {
            int li = base + tid;
            int idx = start + li;
            int val = (li < len) ? g_deg[idx] : 0;
            sbuf[tid] = val;
            __syncthreads();
            #pragma unroll
            for (int off = 1; off < 256; off <<= 1) {
                int t = (tid >= off) ? sbuf[tid - off] : 0;
                __syncthreads();
                sbuf[tid] += t;
                __syncthreads();
            }
            int excl = sbuf[tid] - val;
            if (li < len) {
                int rp = run + excl;
                g_rowptr[idx] = rp;
                g_fill[idx]   = rp;
                g_dinv[idx] = rsqrtf((float)(val + 1));
                if (g_need[idx]) {
                    int s = atomicAdd(&g_cnt, 1);
                    g_slot[idx] = s;
                    g_list[s] = idx;
                }
            }
            int tot = sbuf[255];
            __syncthreads();
            run += tot;
        }
        if (gtid == 0) g_rowptr[NUM_NODES] = E;
    }
}

// ---------------- CSR fill (concurrent with gemm1) ----------------
__global__ __launch_bounds__(256)
void k_fill(const int* __restrict__ src, const int* __restrict__ dst, int E) {
    int e = blockIdx.x * 256 + threadIdx.x;
    if (e < E) {
        int p = atomicAdd(&g_fill[dst[e]], 1);
        g_colidx[p] = src[e];
    }
}

// ---------------- bf16x3 tensor GEMM (split A in-smem) ----------------
#define LDS_STRIDE 136
#define TILE_HALFS (128 * LDS_STRIDE)
#define GEMM_SMEM  (4 * TILE_HALFS * 2)

template <bool FP16IN, bool SCALED, bool COMPACT, bool FOUT>
__global__ __launch_bounds__(256)
void k_gemm(const void* __restrict__ Av,
            const __nv_bfloat16* __restrict__ Bh, const __nv_bfloat16* __restrict__ Bl,
            const float* __restrict__ bias, void* __restrict__ Cv, int Mfix) {
    const int M = COMPACT ? g_cnt : Mfix;
    const int brow = blockIdx.x * 128;
    if (brow >= M) return;

    extern __shared__ __align__(16) __nv_bfloat16 sm[];
    __nv_bfloat16* sAh = sm;
    __nv_bfloat16* sAl = sm + TILE_HALFS;
    __nv_bfloat16* sBh = sm + 2 * TILE_HALFS;
    __nv_bfloat16* sBl = sm + 3 * TILE_HALFS;

    const int tid = threadIdx.x, wid = tid >> 5, lane = tid & 31;

    for (int i = tid; i < 2048; i += 256) {
        int r  = i >> 4;
        int c8 = (i & 15) << 3;
        int d  = r * LDS_STRIDE + c8;
        int grow = brow + r;
        float f[8];
        if (grow < M) {
            if (FP16IN) {
                const __half* A = (const __half*)Av;
                uint4 v = *reinterpret_cast<const uint4*>(A + (size_t)grow * 128 + c8);
                const __half2* hp = reinterpret_cast<const __half2*>(&v);
                #pragma unroll
                for (int q = 0; q < 4; q++) {
                    float2 fq = __half22float2(hp[q]);
                    f[q * 2] = fq.x; f[q * 2 + 1] = fq.y;
                }
            } else {
                const float* A = (const float*)Av;
                float4 a0 = *reinterpret_cast<const float4*>(A + (size_t)grow * 128 + c8);
                float4 a1 = *reinterpret_cast<const float4*>(A + (size_t)grow * 128 + c8 + 4);
                f[0] = a0.x; f[1] = a0.y; f[2] = a0.z; f[3] = a0.w;
                f[4] = a1.x; f[5] = a1.y; f[6] = a1.z; f[7] = a1.w;
            }
        } else {
            #pragma unroll
            for (int q = 0; q < 8; q++) f[q] = 0.f;
        }
        __align__(16) unsigned short hh[8];
        __align__(16) unsigned short ll[8];
        #pragma unroll
        for (int q = 0; q < 8; q++) {
            __nv_bfloat16 hi = __float2bfloat16(f[q]);
            __nv_bfloat16 lo = __float2bfloat16(f[q] - __bfloat162float(hi));
            hh[q] = __bfloat16_as_ushort(hi);
            ll[q] = __bfloat16_as_ushort(lo);
        }
        *reinterpret_cast<ushort4*>(sAh + d)     = *reinterpret_cast<ushort4*>(hh);
        *reinterpret_cast<ushort4*>(sAh + d + 4) = *reinterpret_cast<ushort4*>(hh + 4);
        *reinterpret_cast<ushort4*>(sAl + d)     = *reinterpret_cast<ushort4*>(ll);
        *reinterpret_cast<ushort4*>(sAl + d + 4) = *reinterpret_cast<ushort4*>(ll + 4);
        *reinterpret_cast<uint4*>(sBh + d) =
            *reinterpret_cast<const uint4*>(Bh + (size_t)r * 128 + c8);
        *reinterpret_cast<uint4*>(sBl + d) =
            *reinterpret_cast<const uint4*>(Bl + (size_t)r * 128 + c8);
    }
    __syncthreads();

    const int mb = (wid & 3) * 32;
    const int nb = (wid >> 2) * 64;

    float acc[2][8][4];
    #pragma unroll
    for (int i = 0; i < 2; i++)
        #pragma unroll
        for (int j = 0; j < 8; j++)
            #pragma unroll
            for (int q = 0; q < 4; q++) acc[i][j][q] = 0.0f;

    const int lrow  = lane & 15;
    const int lbyte = (lane >> 4) << 4;

    #pragma unroll
    for (int pass = 0; pass < 3; pass++) {
        const __nv_bfloat16* pA = (pass == 1) ? sAl : sAh;
        const __nv_bfloat16* pB = (pass == 2) ? sBl : sBh;
        #pragma unroll
        for (int k16 = 0; k16 < 8; k16++) {
            int kb = k16 * 16;
            uint32_t a[2][4];
            #pragma unroll
            for (int i = 0; i < 2; i++) {
                uint32_t ad = smem_u32(pA + (mb + i * 16 + lrow) * LDS_STRIDE + kb) + lbyte;
                ldsm_x4(ad, a[i][0], a[i][1], a[i][2], a[i][3]);
            }
            uint32_t b[4][4];
            #pragma unroll
            for (int j = 0; j < 4; j++) {
                uint32_t ad = smem_u32(pB + (nb + j * 16 + lrow) * LDS_STRIDE + kb) + lbyte;
                ldsm_x4(ad, b[j][0], b[j][1], b[j][2], b[j][3]);
            }
            #pragma unroll
            for (int i = 0; i < 2; i++)
                #pragma unroll
                for (int j = 0; j < 4; j++) {
                    mma_bf16(acc[i][j * 2 + 0], a[i], b[j][0], b[j][2]);
                    mma_bf16(acc[i][j * 2 + 1], a[i], b[j][1], b[j][3]);
                }
        }
    }

    const int tr = lane >> 2, tc = (lane & 3) * 2;
    #pragma unroll
    for (int i = 0; i < 2; i++) {
        int row0 = brow + mb + i * 16 + tr;
        float s0 = 1.f, s1 = 1.f;
        if (SCALED) {
            if (row0 < M)     s0 = g_dinv[row0];
            if (row0 + 8 < M) s1 = g_dinv[row0 + 8];
        }
        #pragma unroll
        for (int j = 0; j < 8; j++) {
            int col = nb + j * 8 + tc;
            if (FOUT) {
                float* C = (float*)Cv;
                float bx = bias[col], by = bias[col + 1];
                if (row0 < M) {
                    float2 o = make_float2(acc[i][j][0] + bx, acc[i][j][1] + by);
                    *reinterpret_cast<float2*>(C + (size_t)row0 * 128 + col) = o;
                }
                if (row0 + 8 < M) {
                    float2 o = make_float2(acc[i][j][2] + bx, acc[i][j][3] + by);
                    *reinterpret_cast<float2*>(C + (size_t)(row0 + 8) * 128 + col) = o;
                }
            } else {
                __half* C = (__half*)Cv;
                if (row0 < M)
                    *reinterpret_cast<__half2*>(C + (size_t)row0 * 128 + col) =
                        __floats2half2_rn(acc[i][j][0] * s0, acc[i][j][1] * s0);
                if (row0 + 8 < M)
                    *reinterpret_cast<__half2*>(C + (size_t)(row0 + 8) * 128 + col) =
                        __floats2half2_rn(acc[i][j][2] * s1, acc[i][j][3] * s1);
            }
        }
    }
}

// ---------------- aggregation: 2 rows/LDG.128 + SINGLE fp16 batch chain ----------------
// fl = lane&15 -> 16B feature chunk; half = lane>>4 -> which edge of a pair.
// One fp16 accumulator chain per 32-edge batch; fp32 convert once per batch.
__device__ __forceinline__ void agg_core8(const __half* __restrict__ x, int node, int lane,
                                          float* acc) {
    const uint4* xr = reinterpret_cast<const uint4*>(x);   // 16 uint4 per 128-feat row
    const int fl = lane & 15, half = lane >> 4;

    #pragma unroll
    for (int q = 0; q < 8; q++) acc[q] = 0.f;
    // self term: half 0 only (avoid double count after butterfly)
    {
        uint4 su = xr[(size_t)node * 16 + fl];
        if (half == 0) {
            __half2* sh = reinterpret_cast<__half2*>(&su);
            #pragma unroll
            for (int q = 0; q < 4; q++) {
                float2 f = __half22float2(sh[q]);
                acc[q * 2]     += f.x;
                acc[q * 2 + 1] += f.y;
            }
        }
    }

    const __half2 zero2 = __float2half2_rn(0.f);
    int b = g_rowptr[node], e = g_rowptr[node + 1];
    for (int base = b; base < e; base += 32) {
        int m = min(32, e - base);
        int c = (lane < m) ? g_colidx[base + lane] : 0;
        __half2 ah0 = zero2, ah1 = zero2, ah2 = zero2, ah3 = zero2;   // single chain
        int j = 0;
        // 4 edges/iter: 2 LDG.128, 2 SHFL, 8 HADD2 (pair + chain)
        for (; j + 4 <= m; j += 4) {
            int sA = __shfl_sync(0xFFFFFFFFu, c, j + half);
            int sB = __shfl_sync(0xFFFFFFFFu, c, j + 2 + half);
            uint4 uA = xr[(size_t)sA * 16 + fl];
            uint4 uB = xr[(size_t)sB * 16 + fl];
            __half2* ha = reinterpret_cast<__half2*>(&uA);
            __half2* hb = reinterpret_cast<__half2*>(&uB);
            ah0 = __hadd2(ah0, __hadd2(ha[0], hb[0]));
            ah1 = __hadd2(ah1, __hadd2(ha[1], hb[1]));
            ah2 = __hadd2(ah2, __hadd2(ha[2], hb[2]));
            ah3 = __hadd2(ah3, __hadd2(ha[3], hb[3]));
        }
        // 2 edges
        for (; j + 2 <= m; j += 2) {
            int s = __shfl_sync(0xFFFFFFFFu, c, j + half);
            uint4 u = xr[(size_t)s * 16 + fl];
            __half2* h = reinterpret_cast<__half2*>(&u);
            ah0 = __hadd2(ah0, h[0]); ah1 = __hadd2(ah1, h[1]);
            ah2 = __hadd2(ah2, h[2]); ah3 = __hadd2(ah3, h[3]);
        }
        // odd tail: half 0 only
        if (j < m) {
            int s = __shfl_sync(0xFFFFFFFFu, c, j);
            uint4 u = xr[(size_t)s * 16 + fl];
            if (half == 0) {
                __half2* h = reinterpret_cast<__half2*>(&u);
                ah0 = __hadd2(ah0, h[0]); ah1 = __hadd2(ah1, h[1]);
                ah2 = __hadd2(ah2, h[2]); ah3 = __hadd2(ah3, h[3]);
            }
        }
        // convert once per batch
        float2 f0 = __half22float2(ah0), f1 = __half22float2(ah1);
        float2 f2 = __half22float2(ah2), f3 = __half22float2(ah3);
        acc[0] += f0.x; acc[1] += f0.y;
        acc[2] += f1.x; acc[3] += f1.y;
        acc[4] += f2.x; acc[5] += f2.y;
        acc[6] += f3.x; acc[7] += f3.y;
    }
    // butterfly: merge the two half-warp partials
    #pragma unroll
    for (int q = 0; q < 8; q++)
        acc[q] += __shfl_xor_sync(0xFFFFFFFFu, acc[q], 16);
}

// layer-1 agg: h'[v] = dinv[v] * relu(dinv[v]*acc + b0)
__global__ __launch_bounds__(256, 7)
void k_agg(const __half* __restrict__ x, const float* __restrict__ bias,
           __half* __restrict__ out, int n) {
    int gw   = (blockIdx.x * blockDim.x + threadIdx.x) >> 5;
    int lane = threadIdx.x & 31;
    if (gw >= n) return;
    float acc[8];
    agg_core8(x, gw, lane, acc);
    float dv = g_dinv[gw];
    const int fl = lane & 15, half = lane >> 4;
    const int col = fl * 8 + half * 4;
    float4 bv = *reinterpret_cast<const float4*>(bias + col);
    float o0 = fmaxf(fmaf(acc[half * 4 + 0], dv, bv.x), 0.f) * dv;
    float o1 = fmaxf(fmaf(acc[half * 4 + 1], dv, bv.y), 0.f) * dv;
    float o2 = fmaxf(fmaf(acc[half * 4 + 2], dv, bv.z), 0.f) * dv;
    float o3 = fmaxf(fmaf(acc[half * 4 + 3], dv, bv.w), 0.f) * dv;
    uint2 u;
    __half2 h0 = __floats2half2_rn(o0, o1);
    __half2 h1 = __floats2half2_rn(o2, o3);
    u.x = *reinterpret_cast<uint32_t*>(&h0);
    u.y = *reinterpret_cast<uint32_t*>(&h1);
    *reinterpret_cast<uint2*>(out + (size_t)gw * 128 + col) = u;
}

// layer-2 agg (compact): a2[slot] = dinv[v] * acc  (fp16)
__global__ __launch_bounds__(256, 7)
void k_agg_sel(const __half* __restrict__ x, __half* __restrict__ out) {
    int gw   = (blockIdx.x * blockDim.x + threadIdx.x) >> 5;
    int lane = threadIdx.x & 31;
    if (gw >= g_cnt) return;
    int node = g_list[gw];
    float acc[8];
    agg_core8(x, node, lane, acc);
    float dv = g_dinv[node];
    const int fl = lane & 15, half = lane >> 4;
    const int col = fl * 8 + half * 4;
    uint2 u;
    __half2 h0 = __floats2half2_rn(acc[half * 4 + 0] * dv, acc[half * 4 + 1] * dv);
    __half2 h1 = __floats2half2_rn(acc[half * 4 + 2] * dv, acc[half * 4 + 3] * dv);
    u.x = *reinterpret_cast<uint32_t*>(&h0);
    u.y = *reinterpret_cast<uint32_t*>(&h1);
    *reinterpret_cast<uint2*>(out + (size_t)gw * 128 + col) = u;
}

// ---------------- final gather ----------------
__global__ __launch_bounds__(256)
void k_gather(const float* __restrict__ z, const float* __restrict__ emb,
              const int* __restrict__ seq, float* __restrict__ out, int S) {
    int t = blockIdx.x * blockDim.x + threadIdx.x;
    int pos = t >> 5, lane = t & 31;
    if (pos >= S) return;
    int v = seq[pos];
    const float4* srcp;
    size_t row;
    if (v >= 0) { srcp = reinterpret_cast<const float4*>(z);   row = (size_t)g_slot[v]; }
    else        { srcp = reinterpret_cast<const float4*>(emb); row = (size_t)(v + OFFS + NUM_NODES); }
    reinterpret_cast<float4*>(out)[(size_t)pos * 32 + lane] = srcp[row * 32 + lane];
}

// ---------------- host launch ----------------
extern "C" void kernel_launch(void* const* d_in, const int* in_sizes, int n_in,
                              void* d_out, int out_size) {
    const float* emb = (const float*)d_in[0];
    const float* W0  = (const float*)d_in[1];
    const float* b0  = (const float*)d_in[2];
    const float* W1  = (const float*)d_in[3];
    const float* b1  = (const float*)d_in[4];
    const int*   ei  = (const int*)d_in[5];
    const int*   seq = (const int*)d_in[6];

    int E = in_sizes[5] / 2;
    int S = in_sizes[6];
    const int* src = ei;
    const int* dst = ei + E;

    float *z = nullptr;
    __half *y16 = nullptr, *h16 = nullptr, *a2 = nullptr;
    __nv_bfloat16 *w0h = nullptr, *w0l = nullptr, *w1h = nullptr, *w1l = nullptr;
    cudaGetSymbolAddress((void**)&z,   g_z);
    cudaGetSymbolAddress((void**)&y16, g_y16);
    cudaGetSymbolAddress((void**)&h16, g_h16);
    cudaGetSymbolAddress((void**)&a2,  g_a2);
    cudaGetSymbolAddress((void**)&w0h, g_w0h);
    cudaGetSymbolAddress((void**)&w0l, g_w0l);
    cudaGetSymbolAddress((void**)&w1h, g_w1h);
    cudaGetSymbolAddress((void**)&w1l, g_w1l);

    cudaFuncSetAttribute((const void*)k_gemm<false, true, false, false>,
                         cudaFuncAttributeMaxDynamicSharedMemorySize, GEMM_SMEM);
    cudaFuncSetAttribute((const void*)k_gemm<true, false, true, true>,
                         cudaFuncAttributeMaxDynamicSharedMemorySize, GEMM_SMEM);

    int dev = 0, nsm = 0;
    cudaGetDevice(&dev);
    cudaDeviceGetAttribute(&nsm, cudaDevAttrMultiProcessorCount, dev);
    int nblk = nsm * 4;
    if (nblk > 2048) nblk = 2048;
    int chunk = (NUM_NODES + nblk - 1) / nblk;

    static bool s_init = false;
    static cudaStream_t s_fill;
    static cudaEvent_t s_evA, s_evB;
    if (!s_init) {
        cudaStreamCreateWithFlags(&s_fill, cudaStreamNonBlocking);
        cudaEventCreateWithFlags(&s_evA, cudaEventDisableTiming);
        cudaEventCreateWithFlags(&s_evB, cudaEventDisableTiming);
        s_init = true;
    }

    // 0) prep
    k_prep<<<nblk, 256>>>(W0, W1, dst, seq, E, S, nblk, chunk);
    // fork: fill concurrent with gemm1
    cudaEventRecord(s_evA, 0);
    cudaStreamWaitEvent(s_fill, s_evA, 0);
    k_fill<<<(E + 255) / 256, 256, 0, s_fill>>>(src, dst, E);
    cudaEventRecord(s_evB, s_fill);
    // 1) Y0' = dinv * (emb @ W0)
    k_gemm<false, true, false, false><<<(NUM_NODES + 127) / 128, 256, GEMM_SMEM>>>(
        emb, w0h, w0l, nullptr, y16, NUM_NODES);
    cudaStreamWaitEvent(0, s_evB, 0);
    // 2) h' = dinv * relu(agg(Y0') + b0)
    k_agg<<<(NUM_NODES * 32 + 255) / 256, 256>>>(y16, b0, h16, NUM_NODES);
    // 3) a2 = agg_sel(h')
    k_agg_sel<<<(MAX_SEQ * 32 + 255) / 256, 256>>>(h16, a2);
    // 4) z = a2 @ W1 + b1
    k_gemm<true, false, true, true><<<(MAX_SEQ + 127) / 128, 256, GEMM_SMEM>>>(
        a2, w1h, w1l, b1, z, 0);
    // 5) gather
    k_gather<<<(S * 32 + 255) / 256, 256>>>(z, emb, seq, (float*)d_out, S);
}

// round 16
// speedup vs baseline: 1.1609x; 1.1516x over previous
#include <cuda_runtime.h>
#include <cuda_fp16.h>
#include <cstdint>

#define NUM_NODES 100000
#define HIDDEN    128
#define OFFS      2
#define MAX_E     1700000
#define MAX_SEQ   32768

// ---------------- device scratch ----------------
__device__ int   g_deg[NUM_NODES];
__device__ int   g_fill[NUM_NODES];       // after prep: CSR write cursor (= rowptr)
__device__ int   g_rowptr[NUM_NODES + 1];
__device__ int   g_blksum[2048];
__device__ int   g_colidx[MAX_E];
__device__ float g_dinv[NUM_NODES];
__device__ int   g_need[NUM_NODES];
__device__ int   g_slot[NUM_NODES];
__device__ int   g_list[MAX_SEQ];
__device__ int   g_cnt;
__device__ unsigned g_bar;
__device__ unsigned g_gen;
__device__ __half g_y16[(size_t)NUM_NODES * HIDDEN];
__device__ __half g_h16[(size_t)NUM_NODES * HIDDEN];
__device__ __half g_a2[(size_t)MAX_SEQ * HIDDEN];
__device__ float  g_z[(size_t)MAX_SEQ * HIDDEN];
__device__ __half g_w0h[HIDDEN * HIDDEN];   // W^T [n][k] fp16 hi/lo
__device__ __half g_w0l[HIDDEN * HIDDEN];
__device__ __half g_w1h[HIDDEN * HIDDEN];
__device__ __half g_w1l[HIDDEN * HIDDEN];

// ---------------- helpers ----------------
__device__ __forceinline__ uint32_t smem_u32(const void* p) {
    uint32_t a;
    asm("{ .reg .u64 t; cvta.to.shared.u64 t, %1; cvt.u32.u64 %0, t; }" : "=r"(a) : "l"(p));
    return a;
}
__device__ __forceinline__ void ldsm_x4(uint32_t addr, uint32_t& r0, uint32_t& r1,
                                        uint32_t& r2, uint32_t& r3) {
    asm volatile("ldmatrix.sync.aligned.m8n8.x4.shared.b16 {%0,%1,%2,%3}, [%4];"
                 : "=r"(r0), "=r"(r1), "=r"(r2), "=r"(r3) : "r"(addr));
}
__device__ __forceinline__ void mma_f16(float* c, const uint32_t* a, uint32_t b0, uint32_t b1) {
    asm volatile(
        "mma.sync.aligned.m16n8k16.row.col.f32.f16.f16.f32 "
        "{%0,%1,%2,%3}, {%4,%5,%6,%7}, {%8,%9}, {%0,%1,%2,%3};"
        : "+f"(c[0]), "+f"(c[1]), "+f"(c[2]), "+f"(c[3])
        : "r"(a[0]), "r"(a[1]), "r"(a[2]), "r"(a[3]), "r"(b0), "r"(b1));
}
__device__ __forceinline__ void grid_barrier(int nblk) {
    __syncthreads();
    if (threadIdx.x == 0) {
        __threadfence();
        unsigned gen = *(volatile unsigned*)&g_gen;
        if (atomicAdd(&g_bar, 1u) == (unsigned)nblk - 1u) {
            atomicExch(&g_bar, 0u);
            __threadfence();
            atomicAdd(&g_gen, 1u);
        } else {
            while (*(volatile unsigned*)&g_gen == gen) { __nanosleep(64); }
            __threadfence();
        }
    }
    __syncthreads();
}

// ---------------- persistent prep: everything except CSR fill ----------------
__global__ __launch_bounds__(256, 8)
void k_prep(const float* __restrict__ W0, const float* __restrict__ W1,
            const int* __restrict__ dst, const int* __restrict__ seq,
            int E, int S, int nblk, int chunk) {
    const int tid = threadIdx.x, bid = blockIdx.x;
    const int gtid = bid * 256 + tid;
    const int gstride = nblk * 256;
    __shared__ int sbuf[256];

    for (int i = gtid; i < NUM_NODES; i += gstride) {
        g_deg[i] = 0; g_need[i] = 0;
    }
    if (gtid == 0) g_cnt = 0;
    for (int i = gtid; i < 2 * HIDDEN * HIDDEN; i += gstride) {
        int which = i >> 14, idx = i & 16383;   // idx = k*128+n
        float w = (which ? W1 : W0)[idx];
        int k = idx >> 7, n = idx & 127;
        __half h = __float2half_rn(w);
        (which ? g_w1h : g_w0h)[n * 128 + k] = h;
        (which ? g_w1l : g_w0l)[n * 128 + k] = __float2half_rn(w - __half2float(h));
    }
    grid_barrier(nblk);

    for (int e = gtid; e < E; e += gstride) atomicAdd(&g_deg[dst[e]], 1);
    for (int p = gtid; p < S; p += gstride) {
        int v = seq[p];
        if (v >= 0) g_need[v] = 1;
    }
    grid_barrier(nblk);

    {
        int start = bid * chunk;
        int len = NUM_NODES - start;
        if (len > chunk) len = chunk;
        int acc = 0;
        for (int i = tid; i < len; i += 256) acc += g_deg[start + i];
        sbuf[tid] = acc;
        __syncthreads();
        #pragma unroll
        for (int off = 128; off > 0; off >>= 1) {
            if (tid < off) sbuf[tid] += sbuf[tid + off];
            __syncthreads();
        }
        if (tid == 0) g_blksum[bid] = sbuf[0];
    }
    grid_barrier(nblk);

    if (bid == 0) {
        int ele = (nblk + 255) >> 8;
        int base_i = tid * ele;
        int vals[8];
        int tsum = 0;
        for (int q = 0; q < ele && q < 8; q++) {
            int ii = base_i + q;
            vals[q] = (ii < nblk) ? g_blksum[ii] : 0;
            tsum += vals[q];
        }
        sbuf[tid] = tsum;
        __syncthreads();
        #pragma unroll
        for (int off = 1; off < 256; off <<= 1) {
            int t = (tid >= off) ? sbuf[tid - off] : 0;
            __syncthreads();
            sbuf[tid] += t;
            __syncthreads();
        }
        int run = sbuf[tid] - tsum;
        for (int q = 0; q < ele && q < 8; q++) {
            int ii = base_i + q;
            if (ii < nblk) g_blksum[ii] = run;
            run += vals[q];
        }
    }
    grid_barrier(nblk);

    {
        int start = bid * chunk;
        int len = NUM_NODES - start;
        if (len > chunk) len = chunk;
        if (len < 0) len = 0;
        int run = (start < NUM_NODES) ? g_blksum[bid] : 0;
        for (int base = 0; base < chunk; base += 256) {
            int li = base + tid;
            int idx = start + li;
            int val = (li < len) ? g_deg[idx] : 0;
            sbuf[tid] = val;
            __syncthreads();
            #pragma unroll
            for (int off = 1; off < 256; off <<= 1) {
                int t = (tid >= off) ? sbuf[tid - off] : 0;
                __syncthreads();
                sbuf[tid] += t;
                __syncthreads();
            }
            int excl = sbuf[tid] - val;
            if (li < len) {
                int rp = run + excl;
                g_rowptr[idx] = rp;
                g_fill[idx]   = rp;
                g_dinv[idx] = rsqrtf((float)(val + 1));
                if (g_need[idx]) {
                    int s = atomicAdd(&g_cnt, 1);
                    g_slot[idx] = s;
                    g_list[s] = idx;
                }
            }
            int tot = sbuf[255];
            __syncthreads();
            run += tot;
        }
        if (gtid == 0) g_rowptr[NUM_NODES] = E;
    }
}

// ---------------- CSR fill (concurrent with gemm1) ----------------
__global__ __launch_bounds__(256)
void k_fill(const int* __restrict__ src, const int* __restrict__ dst, int E) {
    int e = blockIdx.x * 256 + threadIdx.x;
    if (e < E) {
        int p = atomicAdd(&g_fill[dst[e]], 1);
        g_colidx[p] = src[e];
    }
}

// ---------------- fp16x2 tensor GEMM: C = A @ (Wh + Wl), A fp16, 3 smem tiles ----------------
#define LDS_STRIDE 136
#define TILE_HALFS (128 * LDS_STRIDE)
#define GEMM_SMEM  (3 * TILE_HALFS * 2)

template <bool FP16IN, bool SCALED, bool COMPACT, bool FOUT>
__global__ __launch_bounds__(256)
void k_gemm(const void* __restrict__ Av,
            const __half* __restrict__ Bh, const __half* __restrict__ Bl,
            const float* __restrict__ bias, void* __restrict__ Cv, int Mfix) {
    const int M = COMPACT ? g_cnt : Mfix;
    const int brow = blockIdx.x * 128;
    if (brow >= M) return;

    extern __shared__ __align__(16) __half sm[];
    __half* sA  = sm;
    __half* sBh = sm + TILE_HALFS;
    __half* sBl = sm + 2 * TILE_HALFS;

    const int tid = threadIdx.x, wid = tid >> 5, lane = tid & 31;

    for (int i = tid; i < 2048; i += 256) {
        int r  = i >> 4;
        int c8 = (i & 15) << 3;
        int d  = r * LDS_STRIDE + c8;
        int grow = brow + r;
        if (FP16IN) {
            uint4 v = make_uint4(0, 0, 0, 0);
            if (grow < M)
                v = *reinterpret_cast<const uint4*>((const __half*)Av + (size_t)grow * 128 + c8);
            *reinterpret_cast<uint4*>(sA + d) = v;
        } else {
            float f[8];
            if (grow < M) {
                const float* A = (const float*)Av;
                float4 a0 = *reinterpret_cast<const float4*>(A + (size_t)grow * 128 + c8);
                float4 a1 = *reinterpret_cast<const float4*>(A + (size_t)grow * 128 + c8 + 4);
                f[0] = a0.x; f[1] = a0.y; f[2] = a0.z; f[3] = a0.w;
                f[4] = a1.x; f[5] = a1.y; f[6] = a1.z; f[7] = a1.w;
            } else {
                #pragma unroll
                for (int q = 0; q < 8; q++) f[q] = 0.f;
            }
            uint4 v;
            __half2 p0 = __floats2half2_rn(f[0], f[1]);
            __half2 p1 = __floats2half2_rn(f[2], f[3]);
            __half2 p2 = __floats2half2_rn(f[4], f[5]);
            __half2 p3 = __floats2half2_rn(f[6], f[7]);
            v.x = *reinterpret_cast<uint32_t*>(&p0);
            v.y = *reinterpret_cast<uint32_t*>(&p1);
            v.z = *reinterpret_cast<uint32_t*>(&p2);
            v.w = *reinterpret_cast<uint32_t*>(&p3);
            *reinterpret_cast<uint4*>(sA + d) = v;
        }
        *reinterpret_cast<uint4*>(sBh + d) =
            *reinterpret_cast<const uint4*>(Bh + (size_t)r * 128 + c8);
        *reinterpret_cast<uint4*>(sBl + d) =
            *reinterpret_cast<const uint4*>(Bl + (size_t)r * 128 + c8);
    }
    __syncthreads();

    const int mb = (wid & 3) * 32;
    const int nb = (wid >> 2) * 64;

    float acc[2][8][4];
    #pragma unroll
    for (int i = 0; i < 2; i++)
        #pragma unroll
        for (int j = 0; j < 8; j++)
            #pragma unroll
            for (int q = 0; q < 4; q++) acc[i][j][q] = 0.0f;

    const int lrow  = lane & 15;
    const int lbyte = (lane >> 4) << 4;

    #pragma unroll
    for (int pass = 0; pass < 2; pass++) {
        const __half* pB = (pass == 1) ? sBl : sBh;
        #pragma unroll
        for (int k16 = 0; k16 < 8; k16++) {
            int kb = k16 * 16;
            uint32_t a[2][4];
            #pragma unroll
            for (int i = 0; i < 2; i++) {
                uint32_t ad = smem_u32(sA + (mb + i * 16 + lrow) * LDS_STRIDE + kb) + lbyte;
                ldsm_x4(ad, a[i][0], a[i][1], a[i][2], a[i][3]);
            }
            uint32_t b[4][4];
            #pragma unroll
            for (int j = 0; j < 4; j++) {
                uint32_t ad = smem_u32(pB + (nb + j * 16 + lrow) * LDS_STRIDE + kb) + lbyte;
                ldsm_x4(ad, b[j][0], b[j][1], b[j][2], b[j][3]);
            }
            #pragma unroll
            for (int i = 0; i < 2; i++)
                #pragma unroll
                for (int j = 0; j < 4; j++) {
                    mma_f16(acc[i][j * 2 + 0], a[i], b[j][0], b[j][2]);
                    mma_f16(acc[i][j * 2 + 1], a[i], b[j][1], b[j][3]);
                }
        }
    }

    const int tr = lane >> 2, tc = (lane & 3) * 2;
    #pragma unroll
    for (int i = 0; i < 2; i++) {
        int row0 = brow + mb + i * 16 + tr;
        float s0 = 1.f, s1 = 1.f;
        if (SCALED) {
            if (row0 < M)     s0 = g_dinv[row0];
            if (row0 + 8 < M) s1 = g_dinv[row0 + 8];
        }
        #pragma unroll
        for (int j = 0; j < 8; j++) {
            int col = nb + j * 8 + tc;
            if (FOUT) {
                float* C = (float*)Cv;
                float bx = bias[col], by = bias[col + 1];
                if (row0 < M) {
                    float2 o = make_float2(acc[i][j][0] + bx, acc[i][j][1] + by);
                    *reinterpret_cast<float2*>(C + (size_t)row0 * 128 + col) = o;
                }
                if (row0 + 8 < M) {
                    float2 o = make_float2(acc[i][j][2] + bx, acc[i][j][3] + by);
                    *reinterpret_cast<float2*>(C + (size_t)(row0 + 8) * 128 + col) = o;
                }
            } else {
                __half* C = (__half*)Cv;
                if (row0 < M)
                    *reinterpret_cast<__half2*>(C + (size_t)row0 * 128 + col) =
                        __floats2half2_rn(acc[i][j][0] * s0, acc[i][j][1] * s0);
                if (row0 + 8 < M)
                    *reinterpret_cast<__half2*>(C + (size_t)(row0 + 8) * 128 + col) =
                        __floats2half2_rn(acc[i][j][2] * s1, acc[i][j][3] * s1);
            }
        }
    }
}

// ---------------- aggregation (R13-exact): 2 rows/LDG.128, pair-then-convert ----------------
__device__ __forceinline__ void agg_core8(const __half* __restrict__ x, int node, int lane,
                                          float* acc) {
    const uint4* xr = reinterpret_cast<const uint4*>(x);   // 16 uint4 per 128-feat row
    const int fl = lane & 15, half = lane >> 4;

    #pragma unroll
    for (int q = 0; q < 8; q++) acc[q] = 0.f;
    // self term: half 0 only (avoid double count after butterfly)
    {
        uint4 su = xr[(size_t)node * 16 + fl];
        if (half == 0) {
            __half2* sh = reinterpret_cast<__half2*>(&su);
            #pragma unroll
            for (int q = 0; q < 4; q++) {
                float2 f = __half22float2(sh[q]);
                acc[q * 2]     += f.x;
                acc[q * 2 + 1] += f.y;
            }
        }
    }

    int b = g_rowptr[node], e = g_rowptr[node + 1];
    for (int base = b; base < e; base += 32) {
        int m = min(32, e - base);
        int c = (lane < m) ? g_colidx[base + lane] : 0;
        int j = 0;
        // 4 edges per iteration: two LDG.128, one fp16 pairing level
        for (; j + 4 <= m; j += 4) {
            int sA = __shfl_sync(0xFFFFFFFFu, c, j + half);
            int sB = __shfl_sync(0xFFFFFFFFu, c, j + 2 + half);
            uint4 uA = xr[(size_t)sA * 16 + fl];
            uint4 uB = xr[(size_t)sB * 16 + fl];
            __half2* ha = reinterpret_cast<__half2*>(&uA);
            __half2* hb = reinterpret_cast<__half2*>(&uB);
            #pragma unroll
            for (int q = 0; q < 4; q++) {
                __half2 p = __hadd2(ha[q], hb[q]);
                float2 f = __half22float2(p);
                acc[q * 2]     += f.x;
                acc[q * 2 + 1] += f.y;
            }
        }
        // 2 edges
        for (; j + 2 <= m; j += 2) {
            int s = __shfl_sync(0xFFFFFFFFu, c, j + half);
            uint4 u = xr[(size_t)s * 16 + fl];
            __half2* h = reinterpret_cast<__half2*>(&u);
            #pragma unroll
            for (int q = 0; q < 4; q++) {
                float2 f = __half22float2(h[q]);
                acc[q * 2]     += f.x;
                acc[q * 2 + 1] += f.y;
            }
        }
        // odd tail: half 0 only
        if (j < m) {
            int s = __shfl_sync(0xFFFFFFFFu, c, j);
            uint4 u = xr[(size_t)s * 16 + fl];
            if (half == 0) {
                __half2* h = reinterpret_cast<__half2*>(&u);
                #pragma unroll
                for (int q = 0; q < 4; q++) {
                    float2 f = __half22float2(h[q]);
                    acc[q * 2]     += f.x;
                    acc[q * 2 + 1] += f.y;
                }
            }
        }
    }
    // butterfly: merge the two half-warp partials
    #pragma unroll
    for (int q = 0; q < 8; q++)
        acc[q] += __shfl_xor_sync(0xFFFFFFFFu, acc[q], 16);
}

// layer-1 agg: h'[v] = dinv[v] * relu(dinv[v]*acc + b0)
__global__ __launch_bounds__(256)
void k_agg(const __half* __restrict__ x, const float* __restrict__ bias,
           __half* __restrict__ out, int n) {
    int gw   = (blockIdx.x * blockDim.x + threadIdx.x) >> 5;
    int lane = threadIdx.x & 31;
    if (gw >= n) return;
    float acc[8];
    agg_core8(x, gw, lane, acc);
    float dv = g_dinv[gw];
    const int fl = lane & 15, half = lane >> 4;
    const int col = fl * 8 + half * 4;
    float4 bv = *reinterpret_cast<const float4*>(bias + col);
    float o0 = fmaxf(fmaf(acc[half * 4 + 0], dv, bv.x), 0.f) * dv;
    float o1 = fmaxf(fmaf(acc[half * 4 + 1], dv, bv.y), 0.f) * dv;
    float o2 = fmaxf(fmaf(acc[half * 4 + 2], dv, bv.z), 0.f) * dv;
    float o3 = fmaxf(fmaf(acc[half * 4 + 3], dv, bv.w), 0.f) * dv;
    uint2 u;
    __half2 h0 = __floats2half2_rn(o0, o1);
    __half2 h1 = __floats2half2_rn(o2, o3);
    u.x = *reinterpret_cast<uint32_t*>(&h0);
    u.y = *reinterpret_cast<uint32_t*>(&h1);
    *reinterpret_cast<uint2*>(out + (size_t)gw * 128 + col) = u;
}

// layer-2 agg (compact): a2[slot] = dinv[v] * acc  (fp16)
__global__ __launch_bounds__(256)
void k_agg_sel(const __half* __restrict__ x, __half* __restrict__ out) {
    int gw   = (blockIdx.x * blockDim.x + threadIdx.x) >> 5;
    int lane = threadIdx.x & 31;
    if (gw >= g_cnt) return;
    int node = g_list[gw];
    float acc[8];
    agg_core8(x, node, lane, acc);
    float dv = g_dinv[node];
    const int fl = lane & 15, half = lane >> 4;
    const int col = fl * 8 + half * 4;
    uint2 u;
    __half2 h0 = __floats2half2_rn(acc[half * 4 + 0] * dv, acc[half * 4 + 1] * dv);
    __half2 h1 = __floats2half2_rn(acc[half * 4 + 2] * dv, acc[half * 4 + 3] * dv);
    u.x = *reinterpret_cast<uint32_t*>(&h0);
    u.y = *reinterpret_cast<uint32_t*>(&h1);
    *reinterpret_cast<uint2*>(out + (size_t)gw * 128 + col) = u;
}

// ---------------- final gather ----------------
__global__ __launch_bounds__(256)
void k_gather(const float* __restrict__ z, const float* __restrict__ emb,
              const int* __restrict__ seq, float* __restrict__ out, int S) {
    int t = blockIdx.x * blockDim.x + threadIdx.x;
    int pos = t >> 5, lane = t & 31;
    if (pos >= S) return;
    int v = seq[pos];
    const float4* srcp;
    size_t row;
    if (v >= 0) { srcp = reinterpret_cast<const float4*>(z);   row = (size_t)g_slot[v]; }
    else        { srcp = reinterpret_cast<const float4*>(emb); row = (size_t)(v + OFFS + NUM_NODES); }
    reinterpret_cast<float4*>(out)[(size_t)pos * 32 + lane] = srcp[row * 32 + lane];
}

// ---------------- host launch ----------------
extern "C" void kernel_launch(void* const* d_in, const int* in_sizes, int n_in,
                              void* d_out, int out_size) {
    const float* emb = (const float*)d_in[0];
    const float* W0  = (const float*)d_in[1];
    const float* b0  = (const float*)d_in[2];
    const float* W1  = (const float*)d_in[3];
    const float* b1  = (const float*)d_in[4];
    const int*   ei  = (const int*)d_in[5];
    const int*   seq = (const int*)d_in[6];

    int E = in_sizes[5] / 2;
    int S = in_sizes[6];
    const int* src = ei;
    const int* dst = ei + E;

    float *z = nullptr;
    __half *y16 = nullptr, *h16 = nullptr, *a2 = nullptr;
    __half *w0h = nullptr, *w0l = nullptr, *w1h = nullptr, *w1l = nullptr;
    cudaGetSymbolAddress((void**)&z,   g_z);
    cudaGetSymbolAddress((void**)&y16, g_y16);
    cudaGetSymbolAddress((void**)&h16, g_h16);
    cudaGetSymbolAddress((void**)&a2,  g_a2);
    cudaGetSymbolAddress((void**)&w0h, g_w0h);
    cudaGetSymbolAddress((void**)&w0l, g_w0l);
    cudaGetSymbolAddress((void**)&w1h, g_w1h);
    cudaGetSymbolAddress((void**)&w1l, g_w1l);

    cudaFuncSetAttribute((const void*)k_gemm<false, true, false, false>,
                         cudaFuncAttributeMaxDynamicSharedMemorySize, GEMM_SMEM);
    cudaFuncSetAttribute((const void*)k_gemm<true, false, true, true>,
                         cudaFuncAttributeMaxDynamicSharedMemorySize, GEMM_SMEM);

    int dev = 0, nsm = 0, occ = 0;
    cudaGetDevice(&dev);
    cudaDeviceGetAttribute(&nsm, cudaDevAttrMultiProcessorCount, dev);
    cudaOccupancyMaxActiveBlocksPerMultiprocessor(&occ, k_prep, 256, 0);
    if (occ < 1) occ = 1;
    if (occ > 8) occ = 8;
    int nblk = nsm * occ;
    if (nblk > 2048) nblk = 2048;
    int chunk = (NUM_NODES + nblk - 1) / nblk;

    static bool s_init = false;
    static cudaStream_t s_fill;
    static cudaEvent_t s_evA, s_evB;
    if (!s_init) {
        cudaStreamCreateWithFlags(&s_fill, cudaStreamNonBlocking);
        cudaEventCreateWithFlags(&s_evA, cudaEventDisableTiming);
        cudaEventCreateWithFlags(&s_evB, cudaEventDisableTiming);
        s_init = true;
    }

    // 0) prep
    k_prep<<<nblk, 256>>>(W0, W1, dst, seq, E, S, nblk, chunk);
    // fork: fill concurrent with gemm1
    cudaEventRecord(s_evA, 0);
    cudaStreamWaitEvent(s_fill, s_evA, 0);
    k_fill<<<(E + 255) / 256, 256, 0, s_fill>>>(src, dst, E);
    cudaEventRecord(s_evB, s_fill);
    // 1) Y0' = dinv * (emb @ W0)   (fp32 in, scaled fp16 out)
    k_gemm<false, true, false, false><<<(NUM_NODES + 127) / 128, 256, GEMM_SMEM>>>(
        emb, w0h, w0l, nullptr, y16, NUM_NODES);
    cudaStreamWaitEvent(0, s_evB, 0);
    // 2) h' = dinv * relu(agg(Y0') + b0)
    k_agg<<<(NUM_NODES * 32 + 255) / 256, 256>>>(y16, b0, h16, NUM_NODES);
    // 3) a2 = agg_sel(h')  (compact, fp16)
    k_agg_sel<<<(MAX_SEQ * 32 + 255) / 256, 256>>>(h16, a2);
    // 4) z = a2 @ W1 + b1  (compact, fp32 out)
    k_gemm<true, false, true, true><<<(MAX_SEQ + 127) / 128, 256, GEMM_SMEM>>>(
        a2, w1h, w1l, b1, z, 0);
    // 5) gather
    k_gather<<<(S * 32 + 255) / 256, 256>>>(z, emb, seq, (float*)d_out, S);
}